// round 8
// baseline (speedup 1.0000x reference)
#include <cuda_runtime.h>
#include <cuda_bf16.h>
#include <cstdint>

// ============================================================================
// DeformableCurrents: e_ss - 2 e_st + e_tt
//   == sum over combined set (src ∪ tar) of K(c_p,c_q)*(w_p.w_q),
//   w = +normal (src), -normal (tar); f symmetric => triangular tiles.
//
// v8: cross-iteration software pipeline. Each jj computes denom(jj),
//   rcp(jj), dot(jj) but ACCUMULATES t(jj-1)*r(jj-1) — so no instruction
//   consumes a same-iteration value with latency beyond a 4-cyc fma.
//   MUFU latency and the denom->rcp gap are hidden by construction.
// ============================================================================

#define THREADS   256
#define NCH       4                  // packed chains per thread
#define IPT       (2 * NCH)          // 8 i-points per thread
#define ICHUNK    (THREADS * IPT)    // 2048
#define TJ        256                // j-subtile (== smem tile)
#define JSUB      (ICHUNK / TJ)      // 8

typedef unsigned long long u64;

__device__ double g_partials[1024];
__device__ unsigned int g_done = 0;

// ---- packed f32x2 helpers ---------------------------------------------------
__device__ __forceinline__ u64 fma2(u64 a, u64 b, u64 c) {
    u64 d; asm("fma.rn.f32x2 %0, %1, %2, %3;" : "=l"(d) : "l"(a), "l"(b), "l"(c));
    return d;
}
__device__ __forceinline__ u64 add2(u64 a, u64 b) {
    u64 d; asm("add.rn.f32x2 %0, %1, %2;" : "=l"(d) : "l"(a), "l"(b));
    return d;
}
__device__ __forceinline__ u64 mul2(u64 a, u64 b) {
    u64 d; asm("mul.rn.f32x2 %0, %1, %2;" : "=l"(d) : "l"(a), "l"(b));
    return d;
}
__device__ __forceinline__ u64 pack2(float lo, float hi) {
    u64 d; asm("mov.b64 %0, {%1, %2};" : "=l"(d) : "f"(lo), "f"(hi));
    return d;
}
__device__ __forceinline__ void unpack2(u64 p, float& lo, float& hi) {
    asm("mov.b64 {%0, %1}, %2;" : "=f"(lo), "=f"(hi) : "l"(p));
}
__device__ __forceinline__ float rcpf(float x) {
    float r; asm("rcp.approx.ftz.f32 %0, %1;" : "=f"(r) : "f"(x));
    return r;
}

// ---- per-point prep (center c, squared-norm a2, weight w) --------------------
__device__ __forceinline__ void make_point(
    int t, int N, int M,
    const float* __restrict__ verts, const float* __restrict__ tnorm,
    const float* __restrict__ tcent, const int* __restrict__ sidx,
    float& cx, float& cy, float& cz, float& a2,
    float& wx, float& wy, float& wz)
{
    cx = 0.f; cy = 0.f; cz = 0.f;
    wx = 0.f; wy = 0.f; wz = 0.f;
    if (t < N) {
        int i0 = sidx[3 * t + 0];
        int i1 = sidx[3 * t + 1];
        int i2 = sidx[3 * t + 2];
        float ax = verts[3 * i0], ay = verts[3 * i0 + 1], az = verts[3 * i0 + 2];
        float bx = verts[3 * i1], by = verts[3 * i1 + 1], bz = verts[3 * i1 + 2];
        float gx = verts[3 * i2], gy = verts[3 * i2 + 1], gz = verts[3 * i2 + 2];
        float e1x = ax - bx, e1y = ay - by, e1z = az - bz;
        float e2x = gx - bx, e2y = gy - by, e2z = gz - bz;
        wx = 0.5f * (e1y * e2z - e1z * e2y);
        wy = 0.5f * (e1z * e2x - e1x * e2z);
        wz = 0.5f * (e1x * e2y - e1y * e2x);
        cx = (ax + bx + gx) * (1.0f / 3.0f);
        cy = (ay + by + gy) * (1.0f / 3.0f);
        cz = (az + bz + gz) * (1.0f / 3.0f);
    } else if (t < N + M) {
        int j = t - N;
        cx = tcent[3 * j];  cy = tcent[3 * j + 1];  cz = tcent[3 * j + 2];
        wx = -tnorm[3 * j]; wy = -tnorm[3 * j + 1]; wz = -tnorm[3 * j + 2];
    }
    // padding: w = 0 -> zero contribution (denom >= 1, rcp safe)
    a2 = cx * cx + cy * cy + cz * cz;
}

// ----------------------------------------------------------------------------
__global__ __launch_bounds__(THREADS, 2)
void fused_kernel(const float* __restrict__ verts,
                  const float* __restrict__ tnorm,
                  const float* __restrict__ tcent,
                  const int*   __restrict__ sidx,
                  int N, int M, int T, int nBlocks,
                  float* __restrict__ out)
{
    // splatted j-subtile: 8 u64 per j (7 used + 1 pad) = 16 KB
    __shared__ __align__(16) u64 sj[TJ * 8];
    __shared__ double rbuf[THREADS];
    __shared__ int s_last;

    const int tid = threadIdx.x;

    // block -> (triangular tile-pair, j-subtile)
    int unit = blockIdx.x / JSUB;
    const int sub = blockIdx.x % JSUB;
    int ti = 0, row = T;
    while (unit >= row) { unit -= row; ti++; row--; }
    const int tj = ti + unit;
    const float scale = (ti == tj) ? 1.0f : 2.0f;

    const int ibase = ti * ICHUNK;
    const int jt    = tj * ICHUNK + sub * TJ;

    // ---- j prep + splat fill (1 j per thread) ----
    {
        int j = jt + tid;
        float cx, cy, cz, a2, wx, wy, wz;
        make_point(j, N, M, verts, tnorm, tcent, sidx, cx, cy, cz, a2, wx, wy, wz);
        u64* s = &sj[tid * 8];
        s[0] = pack2(-2.f * cx, -2.f * cx);
        s[1] = pack2(-2.f * cy, -2.f * cy);
        s[2] = pack2(-2.f * cz, -2.f * cz);
        s[3] = pack2(1.f + a2, 1.f + a2);
        s[4] = pack2(wx, wx);
        s[5] = pack2(wy, wy);
        s[6] = pack2(wz, wz);
    }

    // ---- i prep: IPT=8 points straight into packed registers ----
    u64 pcx[NCH], pcy[NCH], pcz[NCH], pa2[NCH];
    u64 pwx[NCH], pwy[NCH], pwz[NCH], acc[NCH];
#pragma unroll
    for (int c = 0; c < NCH; c++) {
        float cxA, cyA, czA, a2A, wxA, wyA, wzA;
        float cxB, cyB, czB, a2B, wxB, wyB, wzB;
        int iA = ibase + (2 * c + 0) * THREADS + tid;
        int iB = ibase + (2 * c + 1) * THREADS + tid;
        make_point(iA, N, M, verts, tnorm, tcent, sidx, cxA, cyA, czA, a2A, wxA, wyA, wzA);
        make_point(iB, N, M, verts, tnorm, tcent, sidx, cxB, cyB, czB, a2B, wxB, wyB, wzB);
        pcx[c] = pack2(cxA, cxB);
        pcy[c] = pack2(cyA, cyB);
        pcz[c] = pack2(czA, czB);
        pa2[c] = pack2(a2A, a2B);
        pwx[c] = pack2(wxA, wxB);
        pwy[c] = pack2(wyA, wyB);
        pwz[c] = pack2(wzA, wzB);
        acc[c] = 0ull;
    }

    __syncthreads();

    // ---- main pair loop: cross-iteration pipelined ----
    // iteration jj: computes d(jj), r(jj), t(jj); accumulates t(jj-1)*r(jj-1)
    u64 tprev[NCH], rprev[NCH];
#pragma unroll
    for (int c = 0; c < NCH; c++) { tprev[c] = 0ull; rprev[c] = 0ull; }

#pragma unroll 8
    for (int jj = 0; jj < TJ; jj++) {
        const ulonglong2* jp = (const ulonglong2*)&sj[jj * 8];
        const ulonglong2 v0 = jp[0];   // {-2cx, -2cy}
        const ulonglong2 v1 = jp[1];   // {-2cz, b}
        const ulonglong2 v2 = jp[2];   // {wx, wy}
        const ulonglong2 v3 = jp[3];   // {wz, pad}

        // denominators for THIS iteration
        u64 d[NCH];
#pragma unroll
        for (int c = 0; c < NCH; c++) {
            u64 t = add2(pa2[c], v1.y);          // a_i + b_j
            t = fma2(v0.x, pcx[c], t);
            t = fma2(v0.y, pcy[c], t);
            d[c] = fma2(v1.x, pcz[c], t);        // = 1 + |ci-cj|^2
        }
        // accumulate PREVIOUS iteration's contribution (operands long ready)
#pragma unroll
        for (int c = 0; c < NCH; c++)
            acc[c] = fma2(tprev[c], rprev[c], acc[c]);
        // reciprocals for THIS iteration (consumed next iteration)
#pragma unroll
        for (int c = 0; c < NCH; c++) {
            float d0, d1; unpack2(d[c], d0, d1);
            rprev[c] = pack2(rcpf(d0), rcpf(d1));
        }
        // dots for THIS iteration (consumed next iteration)
#pragma unroll
        for (int c = 0; c < NCH; c++) {
            u64 t = mul2(pwx[c], v2.x);
            t = fma2(pwy[c], v2.y, t);
            tprev[c] = fma2(pwz[c], v3.x, t);
        }
    }
    // drain the pipeline: last iteration's contribution
#pragma unroll
    for (int c = 0; c < NCH; c++)
        acc[c] = fma2(tprev[c], rprev[c], acc[c]);

    // ---- deterministic block reduction (double) ----
    double s = 0.0;
#pragma unroll
    for (int c = 0; c < NCH; c++) {
        float a0, a1;
        unpack2(acc[c], a0, a1);
        s += (double)a0 + (double)a1;
    }
    s *= (double)scale;
    rbuf[tid] = s;
    __syncthreads();
#pragma unroll
    for (int off = THREADS / 2; off > 0; off >>= 1) {
        if (tid < off) rbuf[tid] += rbuf[tid + off];
        __syncthreads();
    }
    if (tid == 0) {
        g_partials[blockIdx.x] = rbuf[0];
        __threadfence();
        unsigned int ticket = atomicAdd(&g_done, 1u);
        s_last = (ticket == (unsigned int)(nBlocks - 1)) ? 1 : 0;
    }
    __syncthreads();

    // ---- last block: fixed-order deterministic final reduction ----
    if (s_last) {
        double fs = 0.0;
        for (int k = tid; k < nBlocks; k += THREADS)   // fixed assignment+order
            fs += g_partials[k];
        rbuf[tid] = fs;
        __syncthreads();
#pragma unroll
        for (int off = THREADS / 2; off > 0; off >>= 1) {
            if (tid < off) rbuf[tid] += rbuf[tid + off];
            __syncthreads();
        }
        if (tid == 0) {
            out[0] = (float)rbuf[0];
            g_done = 0;   // self-restore for next graph replay
        }
    }
}

// ----------------------------------------------------------------------------
extern "C" void kernel_launch(void* const* d_in, const int* in_sizes, int n_in,
                              void* d_out, int out_size)
{
    const float* verts = (const float*)d_in[0];   // src_vertices  (V,3)
    const float* tnorm = (const float*)d_in[1];   // tar_normals   (M,3)
    const float* tcent = (const float*)d_in[2];   // tar_centers   (M,3)
    const int*   sidx  = (const int*)  d_in[3];   // src_indices   (N,3)

    const int N = in_sizes[3] / 3;
    const int M = in_sizes[1] / 3;
    const int total = N + M;
    const int total_pad = ((total + ICHUNK - 1) / ICHUNK) * ICHUNK;
    const int T = total_pad / ICHUNK;             // 8 for 16384 points

    const int nBlocks = (T * (T + 1) / 2) * JSUB;   // 36 * 8 = 288
    fused_kernel<<<nBlocks, THREADS>>>(verts, tnorm, tcent, sidx,
                                       N, M, T, nBlocks, (float*)d_out);
}